// round 5
// baseline (speedup 1.0000x reference)
#include <cuda_runtime.h>
#include <cuda_bf16.h>
#include <cstdint>

// ---------------- problem constants ----------------
#define BZn   16
#define TTn   962
#define CCn   384
#define DIn   768
#define DSTn  16
#define DTRn  24
#define XPn   56          // DTR + 2*DSTATE
#define MMn   (BZn*TTn)   // 15392
#define IMG_BLK 1966080   // 80*384*64

// ---------------- scratch (device globals; no allocation allowed) ----------------
__device__ __align__(16) float g_X   [MMn*CCn];
__device__ __align__(16) float g_XLN [MMn*CCn];
__device__ __align__(16) float g_XFC1[MMn*CCn];
__device__ __align__(16) float g_XFLIP[MMn*CCn];
__device__ __align__(16) float g_XZ  [(size_t)MMn*2*DIn];
__device__ __align__(16) float g_XCONV[(size_t)MMn*DIn];
__device__ __align__(16) float g_XDBL[(size_t)MMn*XPn];
__device__ __align__(16) float g_DT  [(size_t)MMn*DIn];
__device__ __align__(16) float g_Y   [(size_t)MMn*DIn];
__device__ __align__(16) float g_FM  [MMn*CCn];
__device__ __align__(16) float g_BM  [MMn*CCn];
__device__ __align__(16) float g_RELU[MMn*CCn];

// ---------------- MUFU-free math helpers ----------------
__device__ __forceinline__ float fexp2(float y){
    y = fminf(fmaxf(y, -126.f), 126.f);
    float n = rintf(y);
    float f = y - n;                       // [-0.5, 0.5]
    float g = f * 0.69314718055994531f;    // |g| <= 0.347
    float p = 1.98412698e-4f;
    p = fmaf(p, g, 1.38888889e-3f);
    p = fmaf(p, g, 8.33333333e-3f);
    p = fmaf(p, g, 4.16666667e-2f);
    p = fmaf(p, g, 1.66666667e-1f);
    p = fmaf(p, g, 0.5f);
    p = fmaf(p, g, 1.0f);
    p = fmaf(p, g, 1.0f);
    return p * __int_as_float(((int)n + 127) << 23);
}
__device__ __forceinline__ float fexp(float x){ return fexp2(x * 1.4426950408889634f); }

__device__ __forceinline__ float frcp_fast(float w){   // w > 0 in all uses
    float r = __int_as_float(0x7EF311C3 - __float_as_int(w));
    r = r * fmaf(-w, r, 2.0f);
    r = r * fmaf(-w, r, 2.0f);
    r = r * fmaf(-w, r, 2.0f);
    return r;
}
__device__ __forceinline__ float silu_f(float x){
    return x * frcp_fast(1.0f + fexp(-x));
}
__device__ __forceinline__ float softplus_f(float x){
    float ax = fabsf(x);
    float e  = fexp(-ax);
    float t  = e * frcp_fast(2.0f + e);    // t <= 1/3
    float t2 = t * t;
    float p  = 2.0f/9.0f;
    p = fmaf(p, t2, 2.0f/7.0f);
    p = fmaf(p, t2, 2.0f/5.0f);
    p = fmaf(p, t2, 2.0f/3.0f);
    p = fmaf(p, t2, 2.0f);
    return fmaxf(x, 0.0f) + p * t;         // max(x,0)+log1p(exp(-|x|))
}

// ---------------- token assembly: X = pos_emb + cross-sensor tokens ----------------
__global__ void assemble_kernel(const float* __restrict__ img,
                                const float* __restrict__ lid,
                                const float* __restrict__ rad,
                                const float* __restrict__ gps,
                                const float* __restrict__ pos)
{
    int c = threadIdx.x;       // 0..383
    int t = blockIdx.x;        // 0..961
    int b = blockIdx.y;        // 0..15
    float v;
    if (t < 960){
        int q = t >> 6, p = t & 63;
        int grp = q / 5, s = q - grp*5;
        int band = c >> 7;                 // 0,1,2
        int code = grp + band; if (code >= 3) code -= 3;
        const float* sel = (code == 0) ? img : (code == 1) ? lid : rad;
        v = sel[((size_t)((b*5 + s)*384 + c) << 6) + p];
    } else {
        v = gps[((size_t)(b*2 + (t-960)))*384 + c];
    }
    g_X[((size_t)(b*TTn + t))*CCn + c] = v + pos[t*CCn + c];
}

// ---------------- LayerNorm (one block per token, 128 threads) ----------------
__global__ void ln_kernel(const float* __restrict__ x, const float* __restrict__ gam,
                          const float* __restrict__ bet, float* __restrict__ out)
{
    int m = blockIdx.x, tid = threadIdx.x;
    const float* row = x + (size_t)m*CCn;
    float v0 = row[tid], v1 = row[tid+128], v2 = row[tid+256];
    float s = v0+v1+v2;
    float q = v0*v0 + v1*v1 + v2*v2;
#pragma unroll
    for (int off=16; off; off>>=1){
        s += __shfl_xor_sync(0xffffffffu, s, off);
        q += __shfl_xor_sync(0xffffffffu, q, off);
    }
    __shared__ float ss[4], sq[4];
    if ((tid & 31) == 0){ ss[tid>>5] = s; sq[tid>>5] = q; }
    __syncthreads();
    s = ss[0]+ss[1]+ss[2]+ss[3];
    q = sq[0]+sq[1]+sq[2]+sq[3];
    float mean = s * (1.0f/384.0f);
    float var  = q * (1.0f/384.0f) - mean*mean;
    float rstd = rsqrtf(var + 1e-5f);
    float* orow = out + (size_t)m*CCn;
    orow[tid]     = (v0-mean)*rstd*gam[tid]     + bet[tid];
    orow[tid+128] = (v1-mean)*rstd*gam[tid+128] + bet[tid+128];
    orow[tid+256] = (v2-mean)*rstd*gam[tid+256] + bet[tid+256];
}

// ---------------- GEMM: Co[m,n] = sum_k A[m,k]*W[n,k] (+bias, +activation) ----------
// EPI: 0=none 1=bias 2=bias+leaky(0.2) 3=bias+softplus
template<int EPI>
__global__ void __launch_bounds__(256)
gemm_tn(const float* __restrict__ A, int lda,
        const float* __restrict__ W,
        const float* __restrict__ bias,
        float* __restrict__ Co,
        int M, int N, int K)
{
    __shared__ __align__(16) float As[2][16][132];
    __shared__ __align__(16) float Ws[2][16][68];
    const int tid = threadIdx.x;
    const int m0 = blockIdx.x * 128;
    const int n0 = blockIdx.y * 64;
    const int tx = tid & 15;
    const int ty = tid >> 4;

    const int ar0 = tid >> 2;       // A rows 0..63 and +64
    const int akq = tid & 3;        // k-quadrant (4 floats each)
    const int wr  = tid >> 2;       // W rows 0..63

    float acc[8][4];
#pragma unroll
    for (int i=0;i<8;i++)
#pragma unroll
        for (int j=0;j<4;j++) acc[i][j] = 0.f;

    const int nkt = (K + 15) >> 4;
    float4 pa0, pa1, pw0;

    {   // prologue: k-tile 0
        int gc = akq*4;
        bool kok = gc < K;
        pa0 = (kok && (m0+ar0)    < M) ? *(const float4*)(A + (size_t)(m0+ar0)*lda + gc)    : make_float4(0,0,0,0);
        pa1 = (kok && (m0+ar0+64) < M) ? *(const float4*)(A + (size_t)(m0+ar0+64)*lda + gc) : make_float4(0,0,0,0);
        pw0 = (kok && (n0+wr)     < N) ? *(const float4*)(W + (size_t)(n0+wr)*K + gc)       : make_float4(0,0,0,0);
        int kr = akq*4;
        As[0][kr+0][ar0] = pa0.x; As[0][kr+1][ar0] = pa0.y; As[0][kr+2][ar0] = pa0.z; As[0][kr+3][ar0] = pa0.w;
        As[0][kr+0][ar0+64] = pa1.x; As[0][kr+1][ar0+64] = pa1.y; As[0][kr+2][ar0+64] = pa1.z; As[0][kr+3][ar0+64] = pa1.w;
        Ws[0][kr+0][wr] = pw0.x; Ws[0][kr+1][wr] = pw0.y; Ws[0][kr+2][wr] = pw0.z; Ws[0][kr+3][wr] = pw0.w;
    }
    __syncthreads();

    for (int kt = 0; kt < nkt; kt++){
        int cur = kt & 1;
        bool more = (kt + 1) < nkt;
        if (more){
            int gc = ((kt+1) << 4) + akq*4;
            bool kok = gc < K;
            pa0 = (kok && (m0+ar0)    < M) ? *(const float4*)(A + (size_t)(m0+ar0)*lda + gc)    : make_float4(0,0,0,0);
            pa1 = (kok && (m0+ar0+64) < M) ? *(const float4*)(A + (size_t)(m0+ar0+64)*lda + gc) : make_float4(0,0,0,0);
            pw0 = (kok && (n0+wr)     < N) ? *(const float4*)(W + (size_t)(n0+wr)*K + gc)       : make_float4(0,0,0,0);
        }
#pragma unroll
        for (int kk=0; kk<16; kk++){
            float4 a0 = *(const float4*)&As[cur][kk][ty*8];
            float4 a1 = *(const float4*)&As[cur][kk][ty*8+4];
            float4 w  = *(const float4*)&Ws[cur][kk][tx*4];
            float av[8] = {a0.x,a0.y,a0.z,a0.w,a1.x,a1.y,a1.z,a1.w};
            float wv[4] = {w.x,w.y,w.z,w.w};
#pragma unroll
            for (int i=0;i<8;i++)
#pragma unroll
                for (int j=0;j<4;j++)
                    acc[i][j] = fmaf(av[i], wv[j], acc[i][j]);
        }
        if (more){
            int nb = cur ^ 1;
            int kr = akq*4;
            As[nb][kr+0][ar0] = pa0.x; As[nb][kr+1][ar0] = pa0.y; As[nb][kr+2][ar0] = pa0.z; As[nb][kr+3][ar0] = pa0.w;
            As[nb][kr+0][ar0+64] = pa1.x; As[nb][kr+1][ar0+64] = pa1.y; As[nb][kr+2][ar0+64] = pa1.z; As[nb][kr+3][ar0+64] = pa1.w;
            Ws[nb][kr+0][wr] = pw0.x; Ws[nb][kr+1][wr] = pw0.y; Ws[nb][kr+2][wr] = pw0.z; Ws[nb][kr+3][wr] = pw0.w;
            __syncthreads();
        }
    }

    int n = n0 + tx*4;
    bool nok = (n + 3) < N;
    float bv[4] = {0.f,0.f,0.f,0.f};
    if (EPI >= 1 && nok){
        float4 bb = *(const float4*)(bias + n);
        bv[0]=bb.x; bv[1]=bb.y; bv[2]=bb.z; bv[3]=bb.w;
    }
#pragma unroll
    for (int i=0;i<8;i++){
        int m = m0 + ty*8 + i;
        if (m < M && nok){
            float vv[4];
#pragma unroll
            for (int j=0;j<4;j++){
                float v = acc[i][j] + bv[j];
                if (EPI == 2) v = (v >= 0.f) ? v : 0.2f*v;
                if (EPI == 3) v = softplus_f(v);
                vv[j] = v;
            }
            float4 o; o.x=vv[0]; o.y=vv[1]; o.z=vv[2]; o.w=vv[3];
            *(float4*)(Co + (size_t)m*N + n) = o;
        }
    }
}

// ---------------- time-flip of XFC1 (per batch) ----------------
__global__ void flip_kernel(){
    int idx = blockIdx.x*blockDim.x + threadIdx.x;   // over MM*96 float4s
    if (idx >= MMn*96) return;
    int row = idx / 96, c4 = idx - row*96;
    int b = row / TTn, t = row - b*TTn;
    ((float4*)g_XFLIP)[idx] =
        ((const float4*)g_XFC1)[(size_t)(b*TTn + (TTn-1-t))*96 + c4];
}

// ---------------- depthwise causal conv (k=4) + SiLU over xz[:, :768] ----------------
__global__ void conv_silu_kernel(const float* __restrict__ cw, const float* __restrict__ cb){
    int idx = blockIdx.x*blockDim.x + threadIdx.x;   // over MM*DI
    if (idx >= MMn*DIn) return;
    int d = idx % DIn;
    int m = idx / DIn;
    int b = m / TTn;
    int t = m - b*TTn;
    const float* base = g_XZ + (size_t)(b*TTn) * (2*DIn) + d;
    float acc = cb[d];
    float w0 = cw[d*4+0], w1 = cw[d*4+1], w2 = cw[d*4+2], w3 = cw[d*4+3];
    if (t >= 3) acc = fmaf(w0, base[(size_t)(t-3)*(2*DIn)], acc);
    if (t >= 2) acc = fmaf(w1, base[(size_t)(t-2)*(2*DIn)], acc);
    if (t >= 1) acc = fmaf(w2, base[(size_t)(t-1)*(2*DIn)], acc);
    acc = fmaf(w3, base[(size_t)t*(2*DIn)], acc);
    g_XCONV[idx] = silu_f(acc);
}

// ---------------- selective scan: 4 lanes x 4 states per (b,d) channel ----------------
__global__ void __launch_bounds__(256)
scan_kernel(const float* __restrict__ a_log, const float* __restrict__ Dp){
    int gtid = blockIdx.x*256 + threadIdx.x;
    int lane = gtid & 3;
    int pidx = gtid >> 2;                 // (b,d) pair index, < 12288 always
    int b = pidx / DIn;
    int d = pidx - b*DIn;

    float cA[4], h[4];
#pragma unroll
    for (int j=0;j<4;j++){
        cA[j] = -fexp(a_log[d*16 + lane + j*4]) * 1.4426950408889634f;  // A*log2(e)
        h[j] = 0.f;
    }
    float Dv = Dp[d];
    int mbase = b * TTn;
    for (int t = 0; t < TTn; t++){
        int m = mbase + t;
        float dtv = g_DT   [(size_t)m*DIn + d];
        float xv  = g_XCONV[(size_t)m*DIn + d];
        float dtx = dtv * xv;
        const float* bc = g_XDBL + (size_t)m*XPn;
        float y = 0.f;
#pragma unroll
        for (int j=0;j<4;j++){
            float Bv = bc[24 + lane + j*4];
            float Cv = bc[40 + lane + j*4];
            float a  = fexp2(dtv * cA[j]);            // exp(dt*A_s)
            h[j] = fmaf(h[j], a, dtx * Bv);
            y    = fmaf(h[j], Cv, y);
        }
        y += __shfl_xor_sync(0xffffffffu, y, 1);
        y += __shfl_xor_sync(0xffffffffu, y, 2);
        if (lane == 0){
            float zv = g_XZ[(size_t)m*(2*DIn) + DIn + d];
            g_Y[(size_t)m*DIn + d] = (y + Dv*xv) * silu_f(zv);
        }
    }
}

// ---------------- combine: X = BM * (RELU + FM) ----------------
__global__ void combine_kernel(){
    int idx = blockIdx.x*blockDim.x + threadIdx.x;   // over MM*96 float4s
    if (idx >= MMn*96) return;
    float4 bm = ((const float4*)g_BM)[idx];
    float4 fm = ((const float4*)g_FM)[idx];
    float4 rl = ((const float4*)g_RELU)[idx];
    float4 o;
    o.x = bm.x*(rl.x+fm.x);
    o.y = bm.y*(rl.y+fm.y);
    o.z = bm.z*(rl.z+fm.z);
    o.w = bm.w*(rl.w+fm.w);
    ((float4*)g_X)[idx] = o;
}

// ---------------- final LN + scatter to outputs ----------------
__global__ void final_kernel(const float* __restrict__ gam, const float* __restrict__ bet,
                             float* __restrict__ out)
{
    int m = blockIdx.x, tid = threadIdx.x;
    int b = m / TTn, t = m - b*TTn;
    const float* row = g_X + (size_t)m*CCn;
    float v0 = row[tid], v1 = row[tid+128], v2 = row[tid+256];
    float s = v0+v1+v2;
    float q = v0*v0 + v1*v1 + v2*v2;
#pragma unroll
    for (int off=16; off; off>>=1){
        s += __shfl_xor_sync(0xffffffffu, s, off);
        q += __shfl_xor_sync(0xffffffffu, q, off);
    }
    __shared__ float ss[4], sq[4];
    if ((tid & 31) == 0){ ss[tid>>5] = s; sq[tid>>5] = q; }
    __syncthreads();
    s = ss[0]+ss[1]+ss[2]+ss[3];
    q = sq[0]+sq[1]+sq[2]+sq[3];
    float mean = s * (1.0f/384.0f);
    float var  = q * (1.0f/384.0f) - mean*mean;
    float rstd = rsqrtf(var + 1e-5f);
    float vs[3] = {v0, v1, v2};
#pragma unroll
    for (int i=0;i<3;i++){
        int c = tid + i*128;
        float val = (vs[i]-mean)*rstd*gam[c] + bet[c];
        size_t dst;
        if (t < 960){
            int qq = t >> 6, p = t & 63;
            int sec = qq / 5, sidx = qq - sec*5;
            dst = (size_t)sec*IMG_BLK + (((size_t)((b*5+sidx)*384 + c)) << 6) + p;
        } else {
            dst = (size_t)3*IMG_BLK + (size_t)(b*2 + (t-960))*384 + c;
        }
        out[dst] = val;
    }
}

// ---------------- launch ----------------
extern "C" void kernel_launch(void* const* d_in, const int* in_sizes, int n_in,
                              void* d_out, int out_size)
{
    const float* img      = (const float*)d_in[0];
    const float* lid      = (const float*)d_in[1];
    const float* rad      = (const float*)d_in[2];
    const float* gps      = (const float*)d_in[3];
    const float* pos      = (const float*)d_in[4];
    const float* ln1_g    = (const float*)d_in[5];
    const float* ln1_b    = (const float*)d_in[6];
    const float* fc1_w    = (const float*)d_in[7];
    const float* fc1_b    = (const float*)d_in[8];
    const float* fc2_w    = (const float*)d_in[9];
    const float* fc2_b    = (const float*)d_in[10];
    const float* in_proj_w= (const float*)d_in[11];
    const float* conv_w   = (const float*)d_in[12];
    const float* conv_b   = (const float*)d_in[13];
    const float* x_proj_w = (const float*)d_in[14];
    const float* dt_proj_w= (const float*)d_in[15];
    const float* dt_proj_b= (const float*)d_in[16];
    const float* A_log    = (const float*)d_in[17];
    const float* D_param  = (const float*)d_in[18];
    const float* out_proj_w=(const float*)d_in[19];
    const float* ln_f_g   = (const float*)d_in[20];
    const float* ln_f_b   = (const float*)d_in[21];

    float *pX, *pXLN, *pXFC1, *pXFLIP, *pXZ, *pXCONV, *pXDBL, *pDT, *pY, *pFM, *pBM, *pRELU;
    cudaGetSymbolAddress((void**)&pX,    g_X);
    cudaGetSymbolAddress((void**)&pXLN,  g_XLN);
    cudaGetSymbolAddress((void**)&pXFC1, g_XFC1);
    cudaGetSymbolAddress((void**)&pXFLIP,g_XFLIP);
    cudaGetSymbolAddress((void**)&pXZ,   g_XZ);
    cudaGetSymbolAddress((void**)&pXCONV,g_XCONV);
    cudaGetSymbolAddress((void**)&pXDBL, g_XDBL);
    cudaGetSymbolAddress((void**)&pDT,   g_DT);
    cudaGetSymbolAddress((void**)&pY,    g_Y);
    cudaGetSymbolAddress((void**)&pFM,   g_FM);
    cudaGetSymbolAddress((void**)&pBM,   g_BM);
    cudaGetSymbolAddress((void**)&pRELU, g_RELU);

    assemble_kernel<<<dim3(TTn, BZn), 384>>>(img, lid, rad, gps, pos);

    const int gm = (MMn + 127) / 128;                // 121
    dim3 g384 (gm, 384/64);
    dim3 g1536(gm, 1536/64);
    dim3 g768 (gm, 768/64);
    dim3 g56  (gm, 1);
    const int EW = (MMn*96 + 255)/256;               // float4 elementwise grids
    const int CW = (MMn*DIn + 255)/256;

    for (int l = 0; l < 4; l++){
        ln_kernel<<<MMn,128>>>(pX, ln1_g + l*CCn, ln1_b + l*CCn, pXLN);
        gemm_tn<1><<<g384,256>>>(pXLN, CCn, fc1_w + (size_t)l*CCn*CCn, fc1_b + l*CCn,
                                 pXFC1, MMn, CCn, CCn);
        flip_kernel<<<EW,256>>>();
        for (int dir = 0; dir < 2; dir++){
            int pd = l*2 + dir;
            const float* Ain = dir ? pXFLIP : pXFC1;
            gemm_tn<0><<<g1536,256>>>(Ain, CCn, in_proj_w + (size_t)pd*2*DIn*CCn, nullptr,
                                      pXZ, MMn, 2*DIn, CCn);
            conv_silu_kernel<<<CW,256>>>(conv_w + (size_t)pd*DIn*4, conv_b + (size_t)pd*DIn);
            gemm_tn<0><<<g56,256>>>(pXCONV, DIn, x_proj_w + (size_t)pd*XPn*DIn, nullptr,
                                    pXDBL, MMn, XPn, DIn);
            gemm_tn<3><<<g768,256>>>(pXDBL, XPn, dt_proj_w + (size_t)pd*DIn*DTRn,
                                     dt_proj_b + (size_t)pd*DIn, pDT, MMn, DIn, DTRn);
            scan_kernel<<<192,256>>>(A_log + (size_t)pd*DIn*DSTn, D_param + (size_t)pd*DIn);
            gemm_tn<0><<<g384,256>>>(pY, DIn, out_proj_w + (size_t)pd*CCn*DIn, nullptr,
                                     dir ? pBM : pFM, MMn, CCn, DIn);
        }
        gemm_tn<2><<<g384,256>>>(pXFLIP, CCn, fc2_w + (size_t)l*CCn*CCn, fc2_b + l*CCn,
                                 pRELU, MMn, CCn, CCn);
        combine_kernel<<<EW,256>>>();
    }

    final_kernel<<<MMn,128>>>(ln_f_g, ln_f_b, (float*)d_out);
}

// round 8
// speedup vs baseline: 1.2465x; 1.2465x over previous
#include <cuda_runtime.h>
#include <cuda_bf16.h>
#include <cstdint>

// ---------------- problem constants ----------------
#define BZn   16
#define TTn   962
#define CCn   384
#define DIn   768
#define DSTn  16
#define DTRn  24
#define XPn   56          // DTR + 2*DSTATE
#define MMn   (BZn*TTn)   // 15392
#define IMG_BLK 1966080   // 80*384*64

// ---------------- scratch (device globals; no allocation allowed) ----------------
__device__ __align__(16) float g_X   [MMn*CCn];
__device__ __align__(16) float g_XLN [MMn*CCn];
__device__ __align__(16) float g_XFC1[MMn*CCn];
__device__ __align__(16) float g_XFLIP[MMn*CCn];
__device__ __align__(16) float g_XZ  [(size_t)MMn*2*DIn];
__device__ __align__(16) float g_XCONV[(size_t)MMn*DIn];
__device__ __align__(16) float g_XDBL[(size_t)MMn*XPn];
__device__ __align__(16) float g_DT  [(size_t)MMn*DIn];
__device__ __align__(16) float g_Y   [(size_t)MMn*DIn];
__device__ __align__(16) float g_FM  [MMn*CCn];
__device__ __align__(16) float g_BM  [MMn*CCn];
__device__ __align__(16) float g_RELU[MMn*CCn];
// bf16 split planes for tensor-core GEMMs
__device__ __align__(16) __nv_bfloat16 g_Ahi[(size_t)MMn*DIn];
__device__ __align__(16) __nv_bfloat16 g_Alo[(size_t)MMn*DIn];
__device__ __align__(16) __nv_bfloat16 g_Whi[1536*384];
__device__ __align__(16) __nv_bfloat16 g_Wlo[1536*384];

// ---------------- MUFU-free math helpers ----------------
__device__ __forceinline__ float fexp2(float y){
    y = fminf(fmaxf(y, -126.f), 126.f);
    float n = rintf(y);
    float f = y - n;
    float g = f * 0.69314718055994531f;
    float p = 1.98412698e-4f;
    p = fmaf(p, g, 1.38888889e-3f);
    p = fmaf(p, g, 8.33333333e-3f);
    p = fmaf(p, g, 4.16666667e-2f);
    p = fmaf(p, g, 1.66666667e-1f);
    p = fmaf(p, g, 0.5f);
    p = fmaf(p, g, 1.0f);
    p = fmaf(p, g, 1.0f);
    return p * __int_as_float(((int)n + 127) << 23);
}
__device__ __forceinline__ float fexp(float x){ return fexp2(x * 1.4426950408889634f); }
__device__ __forceinline__ float frcp_fast(float w){
    float r = __int_as_float(0x7EF311C3 - __float_as_int(w));
    r = r * fmaf(-w, r, 2.0f);
    r = r * fmaf(-w, r, 2.0f);
    r = r * fmaf(-w, r, 2.0f);
    return r;
}
__device__ __forceinline__ float silu_f(float x){ return x * frcp_fast(1.0f + fexp(-x)); }
__device__ __forceinline__ float softplus_f(float x){
    float ax = fabsf(x);
    float e  = fexp(-ax);
    float t  = e * frcp_fast(2.0f + e);
    float t2 = t * t;
    float p  = 2.0f/9.0f;
    p = fmaf(p, t2, 2.0f/7.0f);
    p = fmaf(p, t2, 2.0f/5.0f);
    p = fmaf(p, t2, 2.0f/3.0f);
    p = fmaf(p, t2, 2.0f);
    return fmaxf(x, 0.0f) + p * t;
}

// ---------------- mma / ldmatrix helpers (non-'a' features, sm_80+) ----------------
__device__ __forceinline__ uint32_t sptr(const void* p){
    return (uint32_t)__cvta_generic_to_shared(p);
}
__device__ __forceinline__ void ldm_x4(uint32_t r[4], uint32_t addr){
    asm volatile("ldmatrix.sync.aligned.m8n8.x4.shared.b16 {%0,%1,%2,%3}, [%4];"
        : "=r"(r[0]), "=r"(r[1]), "=r"(r[2]), "=r"(r[3]) : "r"(addr));
}
__device__ __forceinline__ void mma_bf16(float* d, const uint32_t* a, const uint32_t* b){
    asm volatile("mma.sync.aligned.m16n8k16.row.col.f32.bf16.bf16.f32 "
        "{%0,%1,%2,%3}, {%4,%5,%6,%7}, {%8,%9}, {%0,%1,%2,%3};"
        : "+f"(d[0]), "+f"(d[1]), "+f"(d[2]), "+f"(d[3])
        : "r"(a[0]), "r"(a[1]), "r"(a[2]), "r"(a[3]), "r"(b[0]), "r"(b[1]));
}

// ---------------- fp32 -> bf16 hi/lo split ----------------
__global__ void cvt_split_kernel(const float* __restrict__ src,
                                 __nv_bfloat16* __restrict__ hi,
                                 __nv_bfloat16* __restrict__ lo, int n4)
{
    int i = blockIdx.x*blockDim.x + threadIdx.x;
    if (i >= n4) return;
    float4 v = ((const float4*)src)[i];
    __nv_bfloat16 h0 = __float2bfloat16(v.x);
    __nv_bfloat16 h1 = __float2bfloat16(v.y);
    __nv_bfloat16 h2 = __float2bfloat16(v.z);
    __nv_bfloat16 h3 = __float2bfloat16(v.w);
    __nv_bfloat16 l0 = __float2bfloat16(v.x - __bfloat162float(h0));
    __nv_bfloat16 l1 = __float2bfloat16(v.y - __bfloat162float(h1));
    __nv_bfloat16 l2 = __float2bfloat16(v.z - __bfloat162float(h2));
    __nv_bfloat16 l3 = __float2bfloat16(v.w - __bfloat162float(h3));
    __nv_bfloat162* ph = (__nv_bfloat162*)hi;
    __nv_bfloat162* pl = (__nv_bfloat162*)lo;
    ph[i*2]   = __nv_bfloat162(h0, h1);
    ph[i*2+1] = __nv_bfloat162(h2, h3);
    pl[i*2]   = __nv_bfloat162(l0, l1);
    pl[i*2+1] = __nv_bfloat162(l2, l3);
}

// ---------------- HMMA GEMM: Co[m,n] = sum_k A[m,k]*W[n,k] ----------------
// bf16x3 split products into fp32 accumulators via mma.sync.m16n8k16.
// Block tile 128(M) x 128(N), K-chunk 32, 8 warps (4m x 2n), warp tile 32x64.
// EPI: 0=none 1=bias 2=bias+leaky(0.2)
template<int EPI>
__global__ void __launch_bounds__(256)
mma_gemm(const __nv_bfloat16* __restrict__ Ahi, const __nv_bfloat16* __restrict__ Alo,
         const __nv_bfloat16* __restrict__ Whi, const __nv_bfloat16* __restrict__ Wlo,
         const float* __restrict__ bias, float* __restrict__ Co,
         int M, int N, int K)
{
    __shared__ __align__(16) __nv_bfloat16 sA[2][128][40];  // [hi/lo][row][k] pad 40
    __shared__ __align__(16) __nv_bfloat16 sB[2][128][40];

    const int tid = threadIdx.x;
    const int lid = tid & 31;
    const int wid = tid >> 5;
    const int warp_m = wid & 3;        // 0..3 -> 32-row slice
    const int warp_n = wid >> 2;       // 0..1 -> 64-col slice
    const int m0 = blockIdx.x * 128;
    const int n0 = blockIdx.y * 128;

    float acc[2][8][4];
#pragma unroll
    for (int i=0;i<2;i++)
#pragma unroll
        for (int j=0;j<8;j++)
#pragma unroll
            for (int q=0;q<4;q++) acc[i][j][q] = 0.f;

    const int lr = tid >> 2;           // load row 0..63 (2 passes -> 128)
    const int lc = tid & 3;            // 16B chunk within 32 bf16 row

    const int nkc = K >> 5;
    for (int kc = 0; kc < nkc; kc++){
        int kb = kc << 5;
        __syncthreads();
#pragma unroll
        for (int p = 0; p < 2; p++){
            int r = lr + p*64;
            size_t go = (size_t)(m0 + r)*K + kb + lc*8;
            uint4 vh = make_uint4(0,0,0,0), vl = make_uint4(0,0,0,0);
            if (m0 + r < M){ vh = *(const uint4*)(Ahi + go); vl = *(const uint4*)(Alo + go); }
            *(uint4*)&sA[0][r][lc*8] = vh;
            *(uint4*)&sA[1][r][lc*8] = vl;
        }
#pragma unroll
        for (int p = 0; p < 2; p++){
            int r = lr + p*64;
            size_t go = (size_t)(n0 + r)*K + kb + lc*8;
            uint4 vh = make_uint4(0,0,0,0), vl = make_uint4(0,0,0,0);
            if (n0 + r < N){ vh = *(const uint4*)(Whi + go); vl = *(const uint4*)(Wlo + go); }
            *(uint4*)&sB[0][r][lc*8] = vh;
            *(uint4*)&sB[1][r][lc*8] = vl;
        }
        __syncthreads();

#pragma unroll
        for (int kk = 0; kk < 2; kk++){
            uint32_t ah[2][4], al[2][4];
#pragma unroll
            for (int i=0;i<2;i++){
                int arow = warp_m*32 + i*16 + (lid & 15);
                int acol = kk*16 + (lid >> 4)*8;
                ldm_x4(ah[i], sptr(&sA[0][arow][acol]));
                ldm_x4(al[i], sptr(&sA[1][arow][acol]));
            }
#pragma unroll
            for (int jp = 0; jp < 4; jp++){
                uint32_t bh[4], bl[4];
                int brow = warp_n*64 + jp*16 + ((lid >> 4) << 3) + (lid & 7);
                int bcol = kk*16 + ((lid >> 3) & 1)*8;
                ldm_x4(bh, sptr(&sB[0][brow][bcol]));
                ldm_x4(bl, sptr(&sB[1][brow][bcol]));
#pragma unroll
                for (int i=0;i<2;i++){
                    mma_bf16(acc[i][jp*2],   ah[i], &bh[0]);
                    mma_bf16(acc[i][jp*2],   al[i], &bh[0]);
                    mma_bf16(acc[i][jp*2],   ah[i], &bl[0]);
                    mma_bf16(acc[i][jp*2+1], ah[i], &bh[2]);
                    mma_bf16(acc[i][jp*2+1], al[i], &bh[2]);
                    mma_bf16(acc[i][jp*2+1], ah[i], &bl[2]);
                }
            }
        }
    }

    // epilogue: D frag: d0,d1 -> (row t/4, col 2*(t%4)); d2,d3 -> (row t/4+8)
#pragma unroll
    for (int i=0;i<2;i++){
#pragma unroll
        for (int j=0;j<8;j++){
            int r = m0 + warp_m*32 + i*16 + (lid >> 2);
            int c = n0 + warp_n*64 + j*8 + (lid & 3)*2;
            if (c < N){
                float b0 = 0.f, b1 = 0.f;
                if (EPI >= 1){ b0 = bias[c]; b1 = bias[c+1]; }
                float v0 = acc[i][j][0] + b0, v1 = acc[i][j][1] + b1;
                float v2 = acc[i][j][2] + b0, v3 = acc[i][j][3] + b1;
                if (EPI == 2){
                    v0 = (v0 >= 0.f) ? v0 : 0.2f*v0;
                    v1 = (v1 >= 0.f) ? v1 : 0.2f*v1;
                    v2 = (v2 >= 0.f) ? v2 : 0.2f*v2;
                    v3 = (v3 >= 0.f) ? v3 : 0.2f*v3;
                }
                if (r < M)     *(float2*)(Co + (size_t)r*N + c)     = make_float2(v0, v1);
                if (r + 8 < M) *(float2*)(Co + (size_t)(r+8)*N + c) = make_float2(v2, v3);
            }
        }
    }
}

// ---------------- token assembly ----------------
__global__ void assemble_kernel(const float* __restrict__ img,
                                const float* __restrict__ lid,
                                const float* __restrict__ rad,
                                const float* __restrict__ gps,
                                const float* __restrict__ pos)
{
    int c = threadIdx.x;
    int t = blockIdx.x;
    int b = blockIdx.y;
    float v;
    if (t < 960){
        int q = t >> 6, p = t & 63;
        int grp = q / 5, s = q - grp*5;
        int band = c >> 7;
        int code = grp + band; if (code >= 3) code -= 3;
        const float* sel = (code == 0) ? img : (code == 1) ? lid : rad;
        v = sel[((size_t)((b*5 + s)*384 + c) << 6) + p];
    } else {
        v = gps[((size_t)(b*2 + (t-960)))*384 + c];
    }
    g_X[((size_t)(b*TTn + t))*CCn + c] = v + pos[t*CCn + c];
}

// ---------------- LayerNorm ----------------
__global__ void ln_kernel(const float* __restrict__ x, const float* __restrict__ gam,
                          const float* __restrict__ bet, float* __restrict__ out)
{
    int m = blockIdx.x, tid = threadIdx.x;
    const float* row = x + (size_t)m*CCn;
    float v0 = row[tid], v1 = row[tid+128], v2 = row[tid+256];
    float s = v0+v1+v2;
    float q = v0*v0 + v1*v1 + v2*v2;
#pragma unroll
    for (int off=16; off; off>>=1){
        s += __shfl_xor_sync(0xffffffffu, s, off);
        q += __shfl_xor_sync(0xffffffffu, q, off);
    }
    __shared__ float ss[4], sq[4];
    if ((tid & 31) == 0){ ss[tid>>5] = s; sq[tid>>5] = q; }
    __syncthreads();
    s = ss[0]+ss[1]+ss[2]+ss[3];
    q = sq[0]+sq[1]+sq[2]+sq[3];
    float mean = s * (1.0f/384.0f);
    float var  = q * (1.0f/384.0f) - mean*mean;
    float rstd = rsqrtf(var + 1e-5f);
    float* orow = out + (size_t)m*CCn;
    orow[tid]     = (v0-mean)*rstd*gam[tid]     + bet[tid];
    orow[tid+128] = (v1-mean)*rstd*gam[tid+128] + bet[tid+128];
    orow[tid+256] = (v2-mean)*rstd*gam[tid+256] + bet[tid+256];
}

// ---------------- SIMT GEMM (dt_proj only: K=24, softplus epi) ----------------
template<int EPI>
__global__ void __launch_bounds__(256)
gemm_tn(const float* __restrict__ A, int lda,
        const float* __restrict__ W,
        const float* __restrict__ bias,
        float* __restrict__ Co,
        int M, int N, int K)
{
    __shared__ __align__(16) float As[2][16][132];
    __shared__ __align__(16) float Ws[2][16][68];
    const int tid = threadIdx.x;
    const int m0 = blockIdx.x * 128;
    const int n0 = blockIdx.y * 64;
    const int tx = tid & 15;
    const int ty = tid >> 4;
    const int ar0 = tid >> 2;
    const int akq = tid & 3;
    const int wr  = tid >> 2;

    float acc[8][4];
#pragma unroll
    for (int i=0;i<8;i++)
#pragma unroll
        for (int j=0;j<4;j++) acc[i][j] = 0.f;

    const int nkt = (K + 15) >> 4;
    float4 pa0, pa1, pw0;
    {
        int gc = akq*4;
        bool kok = gc < K;
        pa0 = (kok && (m0+ar0)    < M) ? *(const float4*)(A + (size_t)(m0+ar0)*lda + gc)    : make_float4(0,0,0,0);
        pa1 = (kok && (m0+ar0+64) < M) ? *(const float4*)(A + (size_t)(m0+ar0+64)*lda + gc) : make_float4(0,0,0,0);
        pw0 = (kok && (n0+wr)     < N) ? *(const float4*)(W + (size_t)(n0+wr)*K + gc)       : make_float4(0,0,0,0);
        int kr = akq*4;
        As[0][kr+0][ar0] = pa0.x; As[0][kr+1][ar0] = pa0.y; As[0][kr+2][ar0] = pa0.z; As[0][kr+3][ar0] = pa0.w;
        As[0][kr+0][ar0+64] = pa1.x; As[0][kr+1][ar0+64] = pa1.y; As[0][kr+2][ar0+64] = pa1.z; As[0][kr+3][ar0+64] = pa1.w;
        Ws[0][kr+0][wr] = pw0.x; Ws[0][kr+1][wr] = pw0.y; Ws[0][kr+2][wr] = pw0.z; Ws[0][kr+3][wr] = pw0.w;
    }
    __syncthreads();

    for (int kt = 0; kt < nkt; kt++){
        int cur = kt & 1;
        bool more = (kt + 1) < nkt;
        if (more){
            int gc = ((kt+1) << 4) + akq*4;
            bool kok = gc < K;
            pa0 = (kok && (m0+ar0)    < M) ? *(const float4*)(A + (size_t)(m0+ar0)*lda + gc)    : make_float4(0,0,0,0);
            pa1 = (kok && (m0+ar0+64) < M) ? *(const float4*)(A + (size_t)(m0+ar0+64)*lda + gc) : make_float4(0,0,0,0);
            pw0 = (kok && (n0+wr)     < N) ? *(const float4*)(W + (size_t)(n0+wr)*K + gc)       : make_float4(0,0,0,0);
        }
#pragma unroll
        for (int kk=0; kk<16; kk++){
            float4 a0 = *(const float4*)&As[cur][kk][ty*8];
            float4 a1 = *(const float4*)&As[cur][kk][ty*8+4];
            float4 w  = *(const float4*)&Ws[cur][kk][tx*4];
            float av[8] = {a0.x,a0.y,a0.z,a0.w,a1.x,a1.y,a1.z,a1.w};
            float wv[4] = {w.x,w.y,w.z,w.w};
#pragma unroll
            for (int i=0;i<8;i++)
#pragma unroll
                for (int j=0;j<4;j++)
                    acc[i][j] = fmaf(av[i], wv[j], acc[i][j]);
        }
        if (more){
            int nb = cur ^ 1;
            int kr = akq*4;
            As[nb][kr+0][ar0] = pa0.x; As[nb][kr+1][ar0] = pa0.y; As[nb][kr+2][ar0] = pa0.z; As[nb][kr+3][ar0] = pa0.w;
            As[nb][kr+0][ar0+64] = pa1.x; As[nb][kr+1][ar0+64] = pa1.y; As[nb][kr+2][ar0+64] = pa1.z; As[nb][kr+3][ar0+64] = pa1.w;
            Ws[nb][kr+0][wr] = pw0.x; Ws[nb][kr+1][wr] = pw0.y; Ws[nb][kr+2][wr] = pw0.z; Ws[nb][kr+3][wr] = pw0.w;
            __syncthreads();
        }
    }

    int n = n0 + tx*4;
    bool nok = (n + 3) < N;
    float bv[4] = {0.f,0.f,0.f,0.f};
    if (EPI >= 1 && nok){
        float4 bb = *(const float4*)(bias + n);
        bv[0]=bb.x; bv[1]=bb.y; bv[2]=bb.z; bv[3]=bb.w;
    }
#pragma unroll
    for (int i=0;i<8;i++){
        int m = m0 + ty*8 + i;
        if (m < M && nok){
            float vv[4];
#pragma unroll
            for (int j=0;j<4;j++){
                float v = acc[i][j] + bv[j];
                if (EPI == 2) v = (v >= 0.f) ? v : 0.2f*v;
                if (EPI == 3) v = softplus_f(v);
                vv[j] = v;
            }
            float4 o; o.x=vv[0]; o.y=vv[1]; o.z=vv[2]; o.w=vv[3];
            *(float4*)(Co + (size_t)m*N + n) = o;
        }
    }
}

// ---------------- time-flip ----------------
__global__ void flip_kernel(){
    int idx = blockIdx.x*blockDim.x + threadIdx.x;
    if (idx >= MMn*96) return;
    int row = idx / 96, c4 = idx - row*96;
    int b = row / TTn, t = row - b*TTn;
    ((float4*)g_XFLIP)[idx] =
        ((const float4*)g_XFC1)[(size_t)(b*TTn + (TTn-1-t))*96 + c4];
}

// ---------------- depthwise causal conv + SiLU ----------------
__global__ void conv_silu_kernel(const float* __restrict__ cw, const float* __restrict__ cb){
    int idx = blockIdx.x*blockDim.x + threadIdx.x;
    if (idx >= MMn*DIn) return;
    int d = idx % DIn;
    int m = idx / DIn;
    int b = m / TTn;
    int t = m - b*TTn;
    const float* base = g_XZ + (size_t)(b*TTn) * (2*DIn) + d;
    float acc = cb[d];
    float w0 = cw[d*4+0], w1 = cw[d*4+1], w2 = cw[d*4+2], w3 = cw[d*4+3];
    if (t >= 3) acc = fmaf(w0, base[(size_t)(t-3)*(2*DIn)], acc);
    if (t >= 2) acc = fmaf(w1, base[(size_t)(t-2)*(2*DIn)], acc);
    if (t >= 1) acc = fmaf(w2, base[(size_t)(t-1)*(2*DIn)], acc);
    acc = fmaf(w3, base[(size_t)t*(2*DIn)], acc);
    g_XCONV[idx] = silu_f(acc);
}

// ---------------- selective scan ----------------
__global__ void __launch_bounds__(256)
scan_kernel(const float* __restrict__ a_log, const float* __restrict__ Dp){
    int gtid = blockIdx.x*256 + threadIdx.x;
    int lane = gtid & 3;
    int pidx = gtid >> 2;
    int b = pidx / DIn;
    int d = pidx - b*DIn;

    float cA[4], h[4];
#pragma unroll
    for (int j=0;j<4;j++){
        cA[j] = -fexp(a_log[d*16 + lane + j*4]) * 1.4426950408889634f;
        h[j] = 0.f;
    }
    float Dv = Dp[d];
    int mbase = b * TTn;
    for (int t = 0; t < TTn; t++){
        int m = mbase + t;
        float dtv = g_DT   [(size_t)m*DIn + d];
        float xv  = g_XCONV[(size_t)m*DIn + d];
        float dtx = dtv * xv;
        const float* bc = g_XDBL + (size_t)m*XPn;
        float y = 0.f;
#pragma unroll
        for (int j=0;j<4;j++){
            float Bv = bc[24 + lane + j*4];
            float Cv = bc[40 + lane + j*4];
            float a  = fexp2(dtv * cA[j]);
            h[j] = fmaf(h[j], a, dtx * Bv);
            y    = fmaf(h[j], Cv, y);
        }
        y += __shfl_xor_sync(0xffffffffu, y, 1);
        y += __shfl_xor_sync(0xffffffffu, y, 2);
        if (lane == 0){
            float zv = g_XZ[(size_t)m*(2*DIn) + DIn + d];
            g_Y[(size_t)m*DIn + d] = (y + Dv*xv) * silu_f(zv);
        }
    }
}

// ---------------- combine ----------------
__global__ void combine_kernel(){
    int idx = blockIdx.x*blockDim.x + threadIdx.x;
    if (idx >= MMn*96) return;
    float4 bm = ((const float4*)g_BM)[idx];
    float4 fm = ((const float4*)g_FM)[idx];
    float4 rl = ((const float4*)g_RELU)[idx];
    float4 o;
    o.x = bm.x*(rl.x+fm.x);
    o.y = bm.y*(rl.y+fm.y);
    o.z = bm.z*(rl.z+fm.z);
    o.w = bm.w*(rl.w+fm.w);
    ((float4*)g_X)[idx] = o;
}

// ---------------- final LN + scatter ----------------
__global__ void final_kernel(const float* __restrict__ gam, const float* __restrict__ bet,
                             float* __restrict__ out)
{
    int m = blockIdx.x, tid = threadIdx.x;
    int b = m / TTn, t = m - b*TTn;
    const float* row = g_X + (size_t)m*CCn;
    float v0 = row[tid], v1 = row[tid+128], v2 = row[tid+256];
    float s = v0+v1+v2;
    float q = v0*v0 + v1*v1 + v2*v2;
#pragma unroll
    for (int off=16; off; off>>=1){
        s += __shfl_xor_sync(0xffffffffu, s, off);
        q += __shfl_xor_sync(0xffffffffu, q, off);
    }
    __shared__ float ss[4], sq[4];
    if ((tid & 31) == 0){ ss[tid>>5] = s; sq[tid>>5] = q; }
    __syncthreads();
    s = ss[0]+ss[1]+ss[2]+ss[3];
    q = sq[0]+sq[1]+sq[2]+sq[3];
    float mean = s * (1.0f/384.0f);
    float var  = q * (1.0f/384.0f) - mean*mean;
    float rstd = rsqrtf(var + 1e-5f);
    float vs[3] = {v0, v1, v2};
#pragma unroll
    for (int i=0;i<3;i++){
        int c = tid + i*128;
        float val = (vs[i]-mean)*rstd*gam[c] + bet[c];
        size_t dst;
        if (t < 960){
            int qq = t >> 6, p = t & 63;
            int sec = qq / 5, sidx = qq - sec*5;
            dst = (size_t)sec*IMG_BLK + (((size_t)((b*5+sidx)*384 + c)) << 6) + p;
        } else {
            dst = (size_t)3*IMG_BLK + (size_t)(b*2 + (t-960))*384 + c;
        }
        out[dst] = val;
    }
}

// ---------------- launch ----------------
extern "C" void kernel_launch(void* const* d_in, const int* in_sizes, int n_in,
                              void* d_out, int out_size)
{
    const float* img      = (const float*)d_in[0];
    const float* lid      = (const float*)d_in[1];
    const float* rad      = (const float*)d_in[2];
    const float* gps      = (const float*)d_in[3];
    const float* pos      = (const float*)d_in[4];
    const float* ln1_g    = (const float*)d_in[5];
    const float* ln1_b    = (const float*)d_in[6];
    const float* fc1_w    = (const float*)d_in[7];
    const float* fc1_b    = (const float*)d_in[8];
    const float* fc2_w    = (const float*)d_in[9];
    const float* fc2_b    = (const float*)d_in[10];
    const float* in_proj_w= (const float*)d_in[11];
    const float* conv_w   = (const float*)d_in[12];
    const float* conv_b   = (const float*)d_in[13];
    const float* x_proj_w = (const float*)d_in[14];
    const float* dt_proj_w= (const float*)d_in[15];
    const float* dt_proj_b= (const float*)d_in[16];
    const float* A_log    = (const float*)d_in[17];
    const float* D_param  = (const float*)d_in[18];
    const float* out_proj_w=(const float*)d_in[19];
    const float* ln_f_g   = (const float*)d_in[20];
    const float* ln_f_b   = (const float*)d_in[21];

    float *pX, *pXLN, *pXFC1, *pXFLIP, *pXZ, *pXCONV, *pXDBL, *pDT, *pY, *pFM, *pBM, *pRELU;
    __nv_bfloat16 *pAhi, *pAlo, *pWhi, *pWlo;
    cudaGetSymbolAddress((void**)&pX,    g_X);
    cudaGetSymbolAddress((void**)&pXLN,  g_XLN);
    cudaGetSymbolAddress((void**)&pXFC1, g_XFC1);
    cudaGetSymbolAddress((void**)&pXFLIP,g_XFLIP);
    cudaGetSymbolAddress((void**)&pXZ,   g_XZ);
    cudaGetSymbolAddress((void**)&pXCONV,g_XCONV);
    cudaGetSymbolAddress((void**)&pXDBL, g_XDBL);
    cudaGetSymbolAddress((void**)&pDT,   g_DT);
    cudaGetSymbolAddress((void**)&pY,    g_Y);
    cudaGetSymbolAddress((void**)&pFM,   g_FM);
    cudaGetSymbolAddress((void**)&pBM,   g_BM);
    cudaGetSymbolAddress((void**)&pRELU, g_RELU);
    cudaGetSymbolAddress((void**)&pAhi,  g_Ahi);
    cudaGetSymbolAddress((void**)&pAlo,  g_Alo);
    cudaGetSymbolAddress((void**)&pWhi,  g_Whi);
    cudaGetSymbolAddress((void**)&pWlo,  g_Wlo);

    assemble_kernel<<<dim3(TTn, BZn), 384>>>(img, lid, rad, gps, pos);

    const int gm = (MMn + 127) / 128;              // 121
    const int EW = (MMn*96 + 255)/256;
    const int CW = (MMn*DIn + 255)/256;
    dim3 g768s(gm, 768/64);                        // SIMT dt_proj grid

    auto cvt = [&](const float* src, int nelem){
        int n4 = nelem / 4;
        cvt_split_kernel<<<(n4 + 255)/256, 256>>>(src, pAhi, pAlo, n4);
    };
    auto cvtW = [&](const float* src, int nelem){
        int n4 = nelem / 4;
        cvt_split_kernel<<<(n4 + 255)/256, 256>>>(src, pWhi, pWlo, n4);
    };

    for (int l = 0; l < 4; l++){
        ln_kernel<<<MMn,128>>>(pX, ln1_g + l*CCn, ln1_b + l*CCn, pXLN);
        // fc1 (+bias)
        cvt (pXLN, MMn*CCn);
        cvtW(fc1_w + (size_t)l*CCn*CCn, CCn*CCn);
        mma_gemm<1><<<dim3(gm,3),256>>>(pAhi,pAlo,pWhi,pWlo, fc1_b + l*CCn,
                                        pXFC1, MMn, CCn, CCn);
        flip_kernel<<<EW,256>>>();
        for (int dir = 0; dir < 2; dir++){
            int pd = l*2 + dir;
            const float* Ain = dir ? pXFLIP : pXFC1;
            // in_proj (N=1536)
            cvt (Ain, MMn*CCn);
            cvtW(in_proj_w + (size_t)pd*2*DIn*CCn, 2*DIn*CCn);
            mma_gemm<0><<<dim3(gm,12),256>>>(pAhi,pAlo,pWhi,pWlo, nullptr,
                                             pXZ, MMn, 2*DIn, CCn);
            conv_silu_kernel<<<CW,256>>>(conv_w + (size_t)pd*DIn*4, conv_b + (size_t)pd*DIn);
            // x_proj (N=56, K=768)
            cvt (pXCONV, MMn*DIn);
            cvtW(x_proj_w + (size_t)pd*XPn*DIn, XPn*DIn);
            mma_gemm<0><<<dim3(gm,1),256>>>(pAhi,pAlo,pWhi,pWlo, nullptr,
                                            pXDBL, MMn, XPn, DIn);
            // dt_proj (SIMT, K=24, softplus)
            gemm_tn<3><<<g768s,256>>>(pXDBL, XPn, dt_proj_w + (size_t)pd*DIn*DTRn,
                                      dt_proj_b + (size_t)pd*DIn, pDT, MMn, DIn, DTRn);
            scan_kernel<<<192,256>>>(A_log + (size_t)pd*DIn*DSTn, D_param + (size_t)pd*DIn);
            // out_proj (N=384, K=768)
            cvt (pY, MMn*DIn);
            cvtW(out_proj_w + (size_t)pd*CCn*DIn, CCn*DIn);
            mma_gemm<0><<<dim3(gm,3),256>>>(pAhi,pAlo,pWhi,pWlo, nullptr,
                                            dir ? pBM : pFM, MMn, CCn, DIn);
        }
        // fc2 + leaky
        cvt (pXFLIP, MMn*CCn);
        cvtW(fc2_w + (size_t)l*CCn*CCn, CCn*CCn);
        mma_gemm<2><<<dim3(gm,3),256>>>(pAhi,pAlo,pWhi,pWlo, fc2_b + l*CCn,
                                        pRELU, MMn, CCn, CCn);
        combine_kernel<<<EW,256>>>();
    }

    final_kernel<<<MMn,128>>>(ln_f_g, ln_f_b, (float*)d_out);
}